// round 2
// baseline (speedup 1.0000x reference)
#include <cuda_runtime.h>
#include <math.h>

#define BB 4
#define CIN 64
#define CHID 96
#define LL 4096
#define NN 16
#define RR 6
#define KK 4
#define DN 192

// ---------------- static scratch (no allocation anywhere) ----------------
__device__ float g_diff [BB*CIN*LL];
__device__ float g_gate [BB*CIN*LL];
__device__ float g_d1   [BB*LL*CHID];
__device__ float g_xln  [BB*LL*CHID];
__device__ float g_xc   [BB*DN*LL];
__device__ float g_xcv  [BB*DN*LL];
__device__ float g_z    [BB*LL*DN];
__device__ float g_xs   [BB*KK*LL*DN];
__device__ float g_delta[BB*KK*LL*DN];
__device__ float g_bs   [BB*KK*LL*NN];
__device__ float g_cs   [BB*KK*LL*NN];
__device__ float g_ys   [BB*KK*LL*DN];
__device__ float g_yln  [BB*LL*DN];
__device__ float g_dd   [BB*LL*CHID];

__device__ __forceinline__ float sigm(float x){ return 1.f/(1.f+__expf(-x)); }
__device__ __forceinline__ float siluf(float x){ return x*sigm(x); }

// ---------------- kDiff: diff = |post - pre| ----------------
__global__ void kDiff(const float* __restrict__ pre, const float* __restrict__ post){
    int i = blockIdx.x*blockDim.x + threadIdx.x;            // 1M float4's / 4
    const float4 a = ((const float4*)pre)[i];
    const float4 b = ((const float4*)post)[i];
    float4 r;
    r.x = fabsf(b.x-a.x); r.y = fabsf(b.y-a.y);
    r.z = fabsf(b.z-a.z); r.w = fabsf(b.w-a.w);
    ((float4*)g_diff)[i] = r;
}

// ---------------- kGate: g = sigmoid(silu(bn(conv1x1(x)))) ; mode 0 store, 1 multiply ----
__global__ void kGate(const float* __restrict__ x, const float* __restrict__ w,
                      const float* __restrict__ bias, const float* __restrict__ bng,
                      const float* __restrict__ bnb, int mode){
    __shared__ float sW[CIN*CIN];   // (o,c) row-major
    __shared__ float sA[CIN*64];    // [c][p] ; reused as output stage [o][p]
    int b = blockIdx.x >> 6;
    int pix0 = (blockIdx.x & 63) * 64;
    int tid = threadIdx.x;
    for (int j = tid; j < CIN*CIN; j += 256) sW[j] = w[j];
    for (int j = tid; j < CIN*64; j += 256){
        int c = j >> 6, p = j & 63;
        sA[j] = x[(b*CIN + c)*LL + pix0 + p];
    }
    __syncthreads();
    int p = tid & 63, og = tid >> 6;       // 4 groups x 16 outputs
    float acc[16];
    #pragma unroll
    for (int j = 0; j < 16; j++) acc[j] = 0.f;
    for (int kk = 0; kk < CIN; kk++){
        float a = sA[kk*64 + p];
        #pragma unroll
        for (int j = 0; j < 16; j++)
            acc[j] = fmaf(a, sW[(og*16+j)*CIN + kk], acc[j]);
    }
    float res[16];
    #pragma unroll
    for (int j = 0; j < 16; j++){
        int o = og*16 + j;
        float inv = bng[o] * rsqrtf(1.00001f);
        float t = (acc[j] + bias[o]) * inv + bnb[o];
        res[j] = sigm(siluf(t));
    }
    __syncthreads();   // done reading sA
    #pragma unroll
    for (int j = 0; j < 16; j++) sA[(og*16+j)*64 + p] = res[j];
    __syncthreads();
    for (int j = tid; j < CIN*64; j += 256){
        int o = j >> 6, pp = j & 63;
        int idx = (b*CIN + o)*LL + pix0 + pp;
        float v = sA[j];
        if (mode) g_gate[idx] *= v; else g_gate[idx] = v;
    }
}

// ---------------- kB: d1 = silu(bn(down(diff)))  -> (b,pix,96) ----------------
__global__ void kB(const float* __restrict__ w, const float* __restrict__ bias,
                   const float* __restrict__ bng, const float* __restrict__ bnb){
    __shared__ float sW[CHID*CIN];  // (o,c)
    __shared__ float sA[CIN*64];    // [c][p]
    int b = blockIdx.x >> 6;
    int pix0 = (blockIdx.x & 63) * 64;
    int tid = threadIdx.x;
    for (int j = tid; j < CHID*CIN; j += 256) sW[j] = w[j];
    for (int j = tid; j < CIN*64; j += 256){
        int c = j >> 6, p = j & 63;
        sA[j] = g_diff[(b*CIN + c)*LL + pix0 + p];
    }
    __syncthreads();
    int p = tid & 63, og = tid >> 6;  // 4 groups x 24 outputs
    float acc[24];
    #pragma unroll
    for (int j = 0; j < 24; j++) acc[j] = 0.f;
    for (int kk = 0; kk < CIN; kk++){
        float a = sA[kk*64 + p];
        #pragma unroll
        for (int j = 0; j < 24; j++)
            acc[j] = fmaf(a, sW[(og*24+j)*CIN + kk], acc[j]);
    }
    float* dst = &g_d1[(b*LL + pix0 + p)*CHID];
    #pragma unroll
    for (int j = 0; j < 24; j++){
        int o = og*24 + j;
        float inv = bng[o] * rsqrtf(1.00001f);
        float t = (acc[j] + bias[o]) * inv + bnb[o];
        dst[o] = siluf(t);
    }
}

// ---------------- kC: xln = LN(pe(d1))  -> (b,pix,96) ----------------
__global__ void kC(const float* __restrict__ w, const float* __restrict__ bias,
                   const float* __restrict__ lng, const float* __restrict__ lnb){
    __shared__ float sW[CHID*CHID];   // (o,c)
    __shared__ float sA[16*97];       // [p][c]
    __shared__ float sS[16*16], sS2[16*16];
    __shared__ float sM[16], sR[16];
    int b = blockIdx.x >> 8;
    int pix0 = (blockIdx.x & 255) * 16;
    int tid = threadIdx.x;
    for (int j = tid; j < CHID*CHID; j += 256) sW[j] = w[j];
    for (int j = tid; j < 16*CHID; j += 256){
        int p = j / 96, c = j % 96;
        sA[p*97 + c] = g_d1[(b*LL + pix0 + p)*CHID + c];
    }
    __syncthreads();
    int p = tid & 15, og = tid >> 4;   // 16 groups x 6 outputs
    float acc[6];
    #pragma unroll
    for (int j = 0; j < 6; j++) acc[j] = bias[og*6 + j];
    for (int kk = 0; kk < CHID; kk++){
        float a = sA[p*97 + kk];
        #pragma unroll
        for (int j = 0; j < 6; j++)
            acc[j] = fmaf(a, sW[(og*6+j)*CHID + kk], acc[j]);
    }
    float s = 0.f, s2 = 0.f;
    #pragma unroll
    for (int j = 0; j < 6; j++){ s += acc[j]; s2 += acc[j]*acc[j]; }
    sS[p*16 + og] = s;  sS2[p*16 + og] = s2;
    __syncthreads();
    if (tid < 16){
        float ss = 0.f, ss2 = 0.f;
        #pragma unroll
        for (int i = 0; i < 16; i++){ ss += sS[tid*16+i]; ss2 += sS2[tid*16+i]; }
        float m = ss * (1.f/96.f);
        float var = ss2 * (1.f/96.f) - m*m;
        sM[tid] = m;  sR[tid] = rsqrtf(var + 1e-5f);
    }
    __syncthreads();
    float m = sM[p], rstd = sR[p];
    float* dst = &g_xln[(b*LL + pix0 + p)*CHID];
    #pragma unroll
    for (int j = 0; j < 6; j++){
        int o = og*6 + j;
        dst[o] = (acc[j] - m) * rstd * lng[o] + lnb[o];
    }
}

// ---------------- kD: in_proj (96 -> 384). xc -> (b,d,pix), z -> (b,pix,192) ----------------
__global__ void kD(const float* __restrict__ w, const float* __restrict__ bias){
    __shared__ float sA[32*97];    // [p][c]
    __shared__ float sW[64*96];    // chunk (o,c)
    __shared__ float sO[64*33];    // stage [o][p]
    int b = blockIdx.x >> 7;
    int pix0 = (blockIdx.x & 127) * 32;
    int tid = threadIdx.x;
    for (int j = tid; j < 32*CHID; j += 256){
        int p = j / 96, c = j % 96;
        sA[p*97 + c] = g_xln[(b*LL + pix0 + p)*CHID + c];
    }
    int p = tid & 31, og = tid >> 5;   // 8 groups x 8 outputs
    for (int ch = 0; ch < 6; ch++){
        __syncthreads();
        for (int j = tid; j < 64*96; j += 256) sW[j] = w[ch*64*96 + j];
        __syncthreads();
        float acc[8];
        #pragma unroll
        for (int j = 0; j < 8; j++) acc[j] = bias[ch*64 + og*8 + j];
        for (int kk = 0; kk < CHID; kk++){
            float a = sA[p*97 + kk];
            #pragma unroll
            for (int j = 0; j < 8; j++)
                acc[j] = fmaf(a, sW[(og*8+j)*96 + kk], acc[j]);
        }
        #pragma unroll
        for (int j = 0; j < 8; j++) sO[(og*8+j)*33 + p] = acc[j];
        __syncthreads();
        if (ch < 3){   // xc: channel-major
            for (int j = tid; j < 64*32; j += 256){
                int o = j >> 5, pp = j & 31;
                g_xc[(b*DN + ch*64 + o)*LL + pix0 + pp] = sO[o*33 + pp];
            }
        } else {       // z: pixel-major
            for (int j = tid; j < 32*64; j += 256){
                int pp = j >> 6, oz = j & 63;
                g_z[(b*LL + pix0 + pp)*DN + (ch-3)*64 + oz] = sO[oz*33 + pp];
            }
        }
    }
}

// ---------------- kE: depthwise 3x3 conv + bias + silu ----------------
__global__ void kE(const float* __restrict__ cw, const float* __restrict__ cb){
    __shared__ float sT[18*66];
    int bid = blockIdx.x;
    int rt = bid & 3;       // row tile (16 rows each)
    int bd = bid >> 2;      // b*DN + d
    int d  = bd % DN;
    int r0 = rt * 16;
    int tid = threadIdx.x;
    const float* src = g_xc + bd*LL;
    for (int j = tid; j < 18*66; j += 256){
        int r = j / 66 - 1 + r0;
        int c = j % 66 - 1;
        float v = 0.f;
        if (r >= 0 && r < 64 && c >= 0 && c < 64) v = src[r*64 + c];
        sT[j] = v;
    }
    float w9[9];
    #pragma unroll
    for (int i = 0; i < 9; i++) w9[i] = cw[d*9 + i];
    float bz = cb[d];
    __syncthreads();
    for (int j = tid; j < 16*64; j += 256){
        int r = j >> 6, c = j & 63;
        float s = bz;
        #pragma unroll
        for (int ky = 0; ky < 3; ky++)
            #pragma unroll
            for (int kx = 0; kx < 3; kx++)
                s = fmaf(w9[ky*3+kx], sT[(r+ky)*66 + c + kx], s);
        g_xcv[bd*LL + (r0+r)*64 + c] = siluf(s);
    }
}

// ---------------- kX: gather xs (scan order), x_proj, dt GEMM + softplus ----------------
__global__ void kX(const float* __restrict__ xpw, const float* __restrict__ dtw,
                   const float* __restrict__ dtb){
    __shared__ float sxs[DN*17];     // [d][tt]
    __shared__ float sWx[38*DN];     // (c,d)
    __shared__ float sdtw[DN*6];     // (d,r)
    __shared__ float sdt[6*17];      // [r][tt]
    int tile = blockIdx.x & 255;
    int k    = (blockIdx.x >> 8) & 3;
    int b    = blockIdx.x >> 10;
    int t0   = tile * 16;
    int tid  = threadIdx.x;
    int base = (b*KK + k)*LL;

    for (int j = tid; j < 38*DN; j += 256) sWx[j] = xpw[k*38*DN + j];
    for (int j = tid; j < DN*6; j += 256)  sdtw[j] = dtw[k*DN*6 + j];
    for (int j = tid; j < DN*16; j += 256){
        int d = j >> 4, tt = j & 15;
        int t = t0 + tt;
        int pix;
        if (k == 0)      pix = t;
        else if (k == 1) pix = (t & 63)*64 + (t >> 6);
        else if (k == 2) pix = LL - 1 - t;
        else { int tr = LL - 1 - t; pix = (tr & 63)*64 + (tr >> 6); }
        sxs[d*17 + tt] = g_xcv[(b*DN + d)*LL + pix];
    }
    __syncthreads();
    // write xs in scan order (b,k,t,d)
    for (int j = tid; j < DN*16; j += 256){
        int tt = j / 192, d = j % 192;
        g_xs[(base + t0 + tt)*DN + d] = sxs[d*17 + tt];
    }
    // GEMM1: 38 outputs per step
    for (int j = tid; j < 38*16; j += 256){
        int c = j >> 4, tt = j & 15;
        float acc = 0.f;
        for (int dd = 0; dd < DN; dd++)
            acc = fmaf(sxs[dd*17 + tt], sWx[c*DN + dd], acc);
        if (c < RR)            sdt[c*17 + tt] = acc;
        else if (c < RR + NN)  g_bs[(base + t0 + tt)*NN + (c - RR)] = acc;
        else                   g_cs[(base + t0 + tt)*NN + (c - RR - NN)] = acc;
    }
    __syncthreads();
    // GEMM2: delta = softplus(dt_w @ dts + dt_b)
    for (int j = tid; j < DN*16; j += 256){
        int tt = j / 192, d = j % 192;
        float acc = dtb[k*DN + d];
        #pragma unroll
        for (int r = 0; r < RR; r++)
            acc = fmaf(sdt[r*17 + tt], sdtw[d*6 + r], acc);
        float dl = (acc > 20.f) ? acc : log1pf(__expf(acc));
        g_delta[(base + t0 + tt)*DN + d] = dl;
    }
}

// ---------------- kF: selective scan. 4 chains/block (16 lanes each), 64 threads ----------------
__global__ void kF(const float* __restrict__ A_log, const float* __restrict__ Ds){
    __shared__ float sD[16*4], sX[16*4], sB[16*16], sC[16*16], sY[16*4];
    int bid = blockIdx.x;
    int dg = (bid % 48) * 4;
    int k  = (bid / 48) % 4;
    int b  = bid / 192;
    int tid  = threadIdx.x;      // 64
    int half = tid >> 4;         // chain 0..3
    int n    = tid & 15;
    int d    = dg + half;
    int base = (b*KK + k)*LL;

    float a  = -__expf(A_log[(k*DN + d)*NN + n]);
    float Dv = Ds[k*DN + d];
    float h  = 0.f;

    // prefetch regs
    float rD, rX, rB[4], rC[4];
    {   // chunk 0
        int t = tid >> 2, dd = tid & 3;
        rD = g_delta[(base + t)*DN + dg + dd];
        rX = g_xs   [(base + t)*DN + dg + dd];
        #pragma unroll
        for (int i = 0; i < 4; i++){
            int jj = tid + i*64; int tt = jj >> 4, nn = jj & 15;
            rB[i] = g_bs[(base + tt)*NN + nn];
            rC[i] = g_cs[(base + tt)*NN + nn];
        }
    }
    for (int chunk = 0; chunk < 256; chunk++){
        sD[tid] = rD;  sX[tid] = rX;
        #pragma unroll
        for (int i = 0; i < 4; i++){ sB[tid + i*64] = rB[i]; sC[tid + i*64] = rC[i]; }
        __syncthreads();
        if (chunk < 255){
            int t0n = (chunk + 1) * 16;
            int t = tid >> 2, dd = tid & 3;
            rD = g_delta[(base + t0n + t)*DN + dg + dd];
            rX = g_xs   [(base + t0n + t)*DN + dg + dd];
            #pragma unroll
            for (int i = 0; i < 4; i++){
                int jj = tid + i*64; int tt = jj >> 4, nn = jj & 15;
                rB[i] = g_bs[(base + t0n + tt)*NN + nn];
                rC[i] = g_cs[(base + t0n + tt)*NN + nn];
            }
        }
        #pragma unroll
        for (int t = 0; t < 16; t++){
            float dl = sD[t*4 + half];
            float xv = sX[t*4 + half];
            float Bn = sB[t*16 + n];
            float Cn = sC[t*16 + n];
            float e  = __expf(dl * a);
            h = fmaf(e, h, dl * xv * Bn);
            float p = h * Cn;
            p += __shfl_xor_sync(0xffffffffu, p, 8);
            p += __shfl_xor_sync(0xffffffffu, p, 4);
            p += __shfl_xor_sync(0xffffffffu, p, 2);
            p += __shfl_xor_sync(0xffffffffu, p, 1);
            if (n == 0) sY[t*4 + half] = p + Dv * xv;
        }
        __syncthreads();
        {
            int t = tid >> 2, dd = tid & 3;
            g_ys[(base + chunk*16 + t)*DN + dg + dd] = sY[tid];
        }
    }
}

// ---------------- kG: combine 4 directions + out LN + silu(z) gate -> yln ----------------
__global__ void kG(const float* __restrict__ lng, const float* __restrict__ lnb){
    int gw   = (blockIdx.x*blockDim.x + threadIdx.x) >> 5;
    int lane = threadIdx.x & 31;
    for (int q = 0; q < 8; q++){
        int pg = gw*8 + q;
        int b  = pg >> 12;
        int l  = pg & 4095;
        int hh = l >> 6, ww = l & 63;
        int t1 = ww*64 + hh;
        int b4 = b*KK*LL;
        float y[6], zf[6];
        float s = 0.f, s2 = 0.f;
        #pragma unroll
        for (int i = 0; i < 6; i++){
            int dd = lane + i*32;
            float v = g_ys[(b4 + 0*LL + l)*DN + dd]
                    + g_ys[(b4 + 2*LL + (LL-1-l))*DN + dd]
                    + g_ys[(b4 + 1*LL + t1)*DN + dd]
                    + g_ys[(b4 + 3*LL + (LL-1-t1))*DN + dd];
            y[i]  = v;  s += v;  s2 += v*v;
            zf[i] = g_z[(b*LL + l)*DN + dd];
        }
        #pragma unroll
        for (int off = 16; off > 0; off >>= 1){
            s  += __shfl_xor_sync(0xffffffffu, s,  off);
            s2 += __shfl_xor_sync(0xffffffffu, s2, off);
        }
        float m   = s * (1.f/192.f);
        float var = s2 * (1.f/192.f) - m*m;
        float rstd = rsqrtf(var + 1e-5f);
        #pragma unroll
        for (int i = 0; i < 6; i++){
            int dd = lane + i*32;
            float yn = (y[i] - m) * rstd * lng[dd] + lnb[dd];
            g_yln[(b*LL + l)*DN + dd] = yn * siluf(zf[i]);
        }
    }
}

// ---------------- kH: out_proj (192 -> 96) -> g_dd (b,pix,96) ----------------
__global__ void kH(const float* __restrict__ w, const float* __restrict__ bias){
    __shared__ float sA[16*193];   // [p][c]
    __shared__ float sW[32*192];   // chunk (o,c)
    __shared__ float sO[32*17];
    int b = blockIdx.x >> 8;
    int pix0 = (blockIdx.x & 255) * 16;
    int tid = threadIdx.x;
    for (int j = tid; j < 16*DN; j += 256){
        int p = j / 192, c = j % 192;
        sA[p*193 + c] = g_yln[(b*LL + pix0 + p)*DN + c];
    }
    int p = tid & 15, og = tid >> 4;   // 16 groups x 2 outputs
    for (int ch = 0; ch < 3; ch++){
        __syncthreads();
        for (int j = tid; j < 32*192; j += 256) sW[j] = w[ch*32*192 + j];
        __syncthreads();
        float acc[2];
        acc[0] = bias[ch*32 + og*2 + 0];
        acc[1] = bias[ch*32 + og*2 + 1];
        for (int kk = 0; kk < DN; kk++){
            float av = sA[p*193 + kk];
            acc[0] = fmaf(av, sW[(og*2+0)*DN + kk], acc[0]);
            acc[1] = fmaf(av, sW[(og*2+1)*DN + kk], acc[1]);
        }
        sO[(og*2+0)*17 + p] = acc[0];
        sO[(og*2+1)*17 + p] = acc[1];
        __syncthreads();
        for (int j = tid; j < 16*32; j += 256){
            int pp = j >> 5, o = j & 31;
            g_dd[(b*LL + pix0 + pp)*CHID + ch*32 + o] = sO[o*17 + pp];
        }
    }
}

// ---------------- kI: up + bn + silu + residual + gate -> out ----------------
__global__ void kI(const float* __restrict__ w, const float* __restrict__ bias,
                   const float* __restrict__ bng, const float* __restrict__ bnb,
                   float* __restrict__ out){
    __shared__ float sA[32*97];   // [p][c]
    __shared__ float sW[64*96];   // (o,c)
    __shared__ float sO[64*33];
    int b = blockIdx.x >> 7;
    int pix0 = (blockIdx.x & 127) * 32;
    int tid = threadIdx.x;
    for (int j = tid; j < 64*96; j += 256) sW[j] = w[j];
    for (int j = tid; j < 32*CHID; j += 256){
        int p = j / 96, c = j % 96;
        sA[p*97 + c] = g_dd[(b*LL + pix0 + p)*CHID + c];
    }
    __syncthreads();
    int p = tid & 31, og = tid >> 5;   // 8 groups x 8 outputs
    float acc[8];
    #pragma unroll
    for (int j = 0; j < 8; j++) acc[j] = bias[og*8 + j];
    for (int kk = 0; kk < CHID; kk++){
        float a = sA[p*97 + kk];
        #pragma unroll
        for (int j = 0; j < 8; j++)
            acc[j] = fmaf(a, sW[(og*8+j)*96 + kk], acc[j]);
    }
    #pragma unroll
    for (int j = 0; j < 8; j++){
        int o = og*8 + j;
        float inv = bng[o] * rsqrtf(1.00001f);
        float t = acc[j] * inv + bnb[o];
        sO[o*33 + p] = siluf(t);
    }
    __syncthreads();
    for (int j = tid; j < 64*32; j += 256){
        int o = j >> 5, pp = j & 31;
        int idx = (b*CIN + o)*LL + pix0 + pp;
        out[idx] = (sO[o*33 + pp] + g_diff[idx]) * g_gate[idx];
    }
}

// ---------------- launcher ----------------
extern "C" void kernel_launch(void* const* d_in, const int* in_sizes, int n_in,
                              void* d_out, int out_size){
    const float* pre        = (const float*)d_in[0];
    const float* post       = (const float*)d_in[1];
    const float* prepost_w  = (const float*)d_in[2];
    const float* prepost_b  = (const float*)d_in[3];
    const float* prepost_g  = (const float*)d_in[4];
    const float* prepost_bb = (const float*)d_in[5];
    const float* down_w     = (const float*)d_in[6];
    const float* down_b     = (const float*)d_in[7];
    const float* down_g     = (const float*)d_in[8];
    const float* down_bb    = (const float*)d_in[9];
    const float* up_w       = (const float*)d_in[10];
    const float* up_b       = (const float*)d_in[11];
    const float* up_g       = (const float*)d_in[12];
    const float* up_bb      = (const float*)d_in[13];
    const float* pe_w       = (const float*)d_in[14];
    const float* pe_b       = (const float*)d_in[15];
    const float* pe_ln_g    = (const float*)d_in[16];
    const float* pe_ln_b    = (const float*)d_in[17];
    const float* in_proj_w  = (const float*)d_in[18];
    const float* in_proj_b  = (const float*)d_in[19];
    const float* conv_w     = (const float*)d_in[20];
    const float* conv_b     = (const float*)d_in[21];
    const float* x_proj_w   = (const float*)d_in[22];
    const float* dt_w       = (const float*)d_in[23];
    const float* dt_b       = (const float*)d_in[24];
    const float* A_log      = (const float*)d_in[25];
    const float* Ds         = (const float*)d_in[26];
    const float* out_ln_g   = (const float*)d_in[27];
    const float* out_ln_b   = (const float*)d_in[28];
    const float* out_proj_w = (const float*)d_in[29];
    const float* out_proj_b = (const float*)d_in[30];
    float* out = (float*)d_out;

    kDiff<<<BB*CIN*LL/4/256, 256>>>(pre, post);
    kGate<<<BB*(LL/64), 256>>>(pre,  prepost_w, prepost_b, prepost_g, prepost_bb, 0);
    kGate<<<BB*(LL/64), 256>>>(post, prepost_w, prepost_b, prepost_g, prepost_bb, 1);
    kB<<<BB*(LL/64), 256>>>(down_w, down_b, down_g, down_bb);
    kC<<<BB*(LL/16), 256>>>(pe_w, pe_b, pe_ln_g, pe_ln_b);
    kD<<<BB*(LL/32), 256>>>(in_proj_w, in_proj_b);
    kE<<<BB*DN*4, 256>>>(conv_w, conv_b);
    kX<<<BB*KK*(LL/16), 256>>>(x_proj_w, dt_w, dt_b);
    kF<<<BB*KK*(DN/4), 64>>>(A_log, Ds);
    kG<<<256, 256>>>(out_ln_g, out_ln_b);
    kH<<<BB*(LL/16), 256>>>(out_proj_w, out_proj_b);
    kI<<<BB*(LL/32), 256>>>(up_w, up_b, up_g, up_bb, out);
}

// round 3
// speedup vs baseline: 1.2343x; 1.2343x over previous
#include <cuda_runtime.h>
#include <math.h>

#define BB 4
#define CIN 64
#define CHID 96
#define LL 4096
#define NN 16
#define RR 6
#define KK 4
#define DN 192
#define SEG 8
#define SEGLEN 512

// ---------------- static scratch (no allocation anywhere) ----------------
__device__ float g_diff [BB*CIN*LL];
__device__ float g_gate [BB*CIN*LL];
__device__ float g_d1   [BB*LL*CHID];
__device__ float g_xln  [BB*LL*CHID];
__device__ float g_xc   [BB*DN*LL];
__device__ float g_xcv  [BB*DN*LL];
__device__ float g_z    [BB*LL*DN];
__device__ float g_xs   [BB*KK*LL*DN];
__device__ float g_delta[BB*KK*LL*DN];
__device__ float g_bs   [BB*KK*LL*NN];
__device__ float g_cs   [BB*KK*LL*NN];
__device__ float g_ys   [BB*KK*LL*DN];
__device__ float g_yln  [BB*LL*DN];
__device__ float g_dd   [BB*LL*CHID];
// scan split state
__device__ float g_P [BB*KK*DN*(SEG-1)*NN];
__device__ float g_q [BB*KK*DN*(SEG-1)*NN];
__device__ float g_h0[BB*KK*DN*SEG*NN];

__device__ __forceinline__ float sigm(float x){ return 1.f/(1.f+__expf(-x)); }
__device__ __forceinline__ float siluf(float x){ return x*sigm(x); }

// ---------------- kDiff: diff = |post - pre| ----------------
__global__ void kDiff(const float* __restrict__ pre, const float* __restrict__ post){
    int i = blockIdx.x*blockDim.x + threadIdx.x;
    const float4 a = ((const float4*)pre)[i];
    const float4 b = ((const float4*)post)[i];
    float4 r;
    r.x = fabsf(b.x-a.x); r.y = fabsf(b.y-a.y);
    r.z = fabsf(b.z-a.z); r.w = fabsf(b.w-a.w);
    ((float4*)g_diff)[i] = r;
}

// ---------------- kGate2: g_gate = sig(silu(bn(W@pre))) * sig(silu(bn(W@post))) ----------
__global__ void kGate2(const float* __restrict__ pre, const float* __restrict__ post,
                       const float* __restrict__ w, const float* __restrict__ bias,
                       const float* __restrict__ bng, const float* __restrict__ bnb){
    __shared__ float sW[CIN*CIN];   // 16KB (o,c)
    __shared__ float sP[CIN*32];    // [c][p]
    __shared__ float sQ[CIN*32];
    __shared__ float sO[CIN*32];    // [o][p]
    int b = blockIdx.x >> 7;
    int pix0 = (blockIdx.x & 127) * 32;
    int tid = threadIdx.x;
    for (int j = tid; j < CIN*CIN; j += 256) sW[j] = w[j];
    for (int j = tid; j < CIN*32; j += 256){
        int c = j >> 5, p = j & 31;
        int idx = (b*CIN + c)*LL + pix0 + p;
        sP[j] = pre[idx];
        sQ[j] = post[idx];
    }
    __syncthreads();
    int p = tid & 31, og = tid >> 5;     // 8 groups x 8 outputs
    float a1[8], a2[8];
    #pragma unroll
    for (int j = 0; j < 8; j++){ a1[j] = 0.f; a2[j] = 0.f; }
    for (int kk = 0; kk < CIN; kk++){
        float x1 = sP[kk*32 + p];
        float x2 = sQ[kk*32 + p];
        #pragma unroll
        for (int j = 0; j < 8; j++){
            float wv = sW[(og*8+j)*CIN + kk];
            a1[j] = fmaf(x1, wv, a1[j]);
            a2[j] = fmaf(x2, wv, a2[j]);
        }
    }
    #pragma unroll
    for (int j = 0; j < 8; j++){
        int o = og*8 + j;
        float inv = bng[o] * rsqrtf(1.00001f);
        float bz  = bias[o];
        float bb  = bnb[o];
        float t1 = (a1[j] + bz) * inv + bb;
        float t2 = (a2[j] + bz) * inv + bb;
        sO[o*32 + p] = sigm(siluf(t1)) * sigm(siluf(t2));
    }
    __syncthreads();
    for (int j = tid; j < CIN*32; j += 256){
        int o = j >> 5, pp = j & 31;
        g_gate[(b*CIN + o)*LL + pix0 + pp] = sO[j];
    }
}

// ---------------- kB: d1 = silu(bn(down(diff)))  -> (b,pix,96) ----------------
__global__ void kB(const float* __restrict__ w, const float* __restrict__ bias,
                   const float* __restrict__ bng, const float* __restrict__ bnb){
    __shared__ float sW[CHID*CIN];  // 24KB (o,c)
    __shared__ float sA[CIN*32];    // [c][p]
    int b = blockIdx.x >> 7;
    int pix0 = (blockIdx.x & 127) * 32;
    int tid = threadIdx.x;
    for (int j = tid; j < CHID*CIN; j += 256) sW[j] = w[j];
    for (int j = tid; j < CIN*32; j += 256){
        int c = j >> 5, p = j & 31;
        sA[j] = g_diff[(b*CIN + c)*LL + pix0 + p];
    }
    __syncthreads();
    int p = tid & 31, og = tid >> 5;  // 8 groups x 12 outputs
    float acc[12];
    #pragma unroll
    for (int j = 0; j < 12; j++) acc[j] = 0.f;
    for (int kk = 0; kk < CIN; kk++){
        float a = sA[kk*32 + p];
        #pragma unroll
        for (int j = 0; j < 12; j++)
            acc[j] = fmaf(a, sW[(og*12+j)*CIN + kk], acc[j]);
    }
    float res[12];
    #pragma unroll
    for (int j = 0; j < 12; j++){
        int o = og*12 + j;
        float inv = bng[o] * rsqrtf(1.00001f);
        float t = (acc[j] + bias[o]) * inv + bnb[o];
        res[j] = siluf(t);
    }
    float4* dst = (float4*)&g_d1[(b*LL + pix0 + p)*CHID + og*12];
    #pragma unroll
    for (int v = 0; v < 3; v++)
        dst[v] = make_float4(res[v*4], res[v*4+1], res[v*4+2], res[v*4+3]);
}

// ---------------- kC: xln = LN(pe(d1))  -> (b,pix,96) ----------------
__global__ void kC(const float* __restrict__ w, const float* __restrict__ bias,
                   const float* __restrict__ lng, const float* __restrict__ lnb){
    __shared__ float sW[CHID*CHID];
    __shared__ float sA[16*97];
    __shared__ float sS[16*16], sS2[16*16];
    __shared__ float sM[16], sR[16];
    int b = blockIdx.x >> 8;
    int pix0 = (blockIdx.x & 255) * 16;
    int tid = threadIdx.x;
    for (int j = tid; j < CHID*CHID; j += 256) sW[j] = w[j];
    for (int j = tid; j < 16*CHID; j += 256){
        int p = j / 96, c = j % 96;
        sA[p*97 + c] = g_d1[(b*LL + pix0 + p)*CHID + c];
    }
    __syncthreads();
    int p = tid & 15, og = tid >> 4;
    float acc[6];
    #pragma unroll
    for (int j = 0; j < 6; j++) acc[j] = bias[og*6 + j];
    for (int kk = 0; kk < CHID; kk++){
        float a = sA[p*97 + kk];
        #pragma unroll
        for (int j = 0; j < 6; j++)
            acc[j] = fmaf(a, sW[(og*6+j)*CHID + kk], acc[j]);
    }
    float s = 0.f, s2 = 0.f;
    #pragma unroll
    for (int j = 0; j < 6; j++){ s += acc[j]; s2 += acc[j]*acc[j]; }
    sS[p*16 + og] = s;  sS2[p*16 + og] = s2;
    __syncthreads();
    if (tid < 16){
        float ss = 0.f, ss2 = 0.f;
        #pragma unroll
        for (int i = 0; i < 16; i++){ ss += sS[tid*16+i]; ss2 += sS2[tid*16+i]; }
        float m = ss * (1.f/96.f);
        float var = ss2 * (1.f/96.f) - m*m;
        sM[tid] = m;  sR[tid] = rsqrtf(var + 1e-5f);
    }
    __syncthreads();
    float m = sM[p], rstd = sR[p];
    float* dst = &g_xln[(b*LL + pix0 + p)*CHID];
    #pragma unroll
    for (int j = 0; j < 6; j++){
        int o = og*6 + j;
        dst[o] = (acc[j] - m) * rstd * lng[o] + lnb[o];
    }
}

// ---------------- kD: in_proj (96 -> 384). xc -> (b,d,pix), z -> (b,pix,192) ----------------
__global__ void kD(const float* __restrict__ w, const float* __restrict__ bias){
    __shared__ float sA[32*97];
    __shared__ float sW[64*96];
    __shared__ float sO[64*33];
    int b = blockIdx.x >> 7;
    int pix0 = (blockIdx.x & 127) * 32;
    int tid = threadIdx.x;
    for (int j = tid; j < 32*CHID; j += 256){
        int p = j / 96, c = j % 96;
        sA[p*97 + c] = g_xln[(b*LL + pix0 + p)*CHID + c];
    }
    int p = tid & 31, og = tid >> 5;
    for (int ch = 0; ch < 6; ch++){
        __syncthreads();
        for (int j = tid; j < 64*96; j += 256) sW[j] = w[ch*64*96 + j];
        __syncthreads();
        float acc[8];
        #pragma unroll
        for (int j = 0; j < 8; j++) acc[j] = bias[ch*64 + og*8 + j];
        for (int kk = 0; kk < CHID; kk++){
            float a = sA[p*97 + kk];
            #pragma unroll
            for (int j = 0; j < 8; j++)
                acc[j] = fmaf(a, sW[(og*8+j)*96 + kk], acc[j]);
        }
        #pragma unroll
        for (int j = 0; j < 8; j++) sO[(og*8+j)*33 + p] = acc[j];
        __syncthreads();
        if (ch < 3){
            for (int j = tid; j < 64*32; j += 256){
                int o = j >> 5, pp = j & 31;
                g_xc[(b*DN + ch*64 + o)*LL + pix0 + pp] = sO[o*33 + pp];
            }
        } else {
            for (int j = tid; j < 32*64; j += 256){
                int pp = j >> 6, oz = j & 63;
                g_z[(b*LL + pix0 + pp)*DN + (ch-3)*64 + oz] = sO[oz*33 + pp];
            }
        }
    }
}

// ---------------- kE: depthwise 3x3 conv + bias + silu ----------------
__global__ void kE(const float* __restrict__ cw, const float* __restrict__ cb){
    __shared__ float sT[18*66];
    int bid = blockIdx.x;
    int rt = bid & 3;
    int bd = bid >> 2;
    int d  = bd % DN;
    int r0 = rt * 16;
    int tid = threadIdx.x;
    const float* src = g_xc + bd*LL;
    for (int j = tid; j < 18*66; j += 256){
        int r = j / 66 - 1 + r0;
        int c = j % 66 - 1;
        float v = 0.f;
        if (r >= 0 && r < 64 && c >= 0 && c < 64) v = src[r*64 + c];
        sT[j] = v;
    }
    float w9[9];
    #pragma unroll
    for (int i = 0; i < 9; i++) w9[i] = cw[d*9 + i];
    float bz = cb[d];
    __syncthreads();
    for (int j = tid; j < 16*64; j += 256){
        int r = j >> 6, c = j & 63;
        float s = bz;
        #pragma unroll
        for (int ky = 0; ky < 3; ky++)
            #pragma unroll
            for (int kx = 0; kx < 3; kx++)
                s = fmaf(w9[ky*3+kx], sT[(r+ky)*66 + c + kx], s);
        g_xcv[bd*LL + (r0+r)*64 + c] = siluf(s);
    }
}

// ---------------- kX: gather xs (scan order), x_proj, dt GEMM + softplus ----------------
__global__ void kX(const float* __restrict__ xpw, const float* __restrict__ dtw,
                   const float* __restrict__ dtb){
    __shared__ float sxs[DN*17];
    __shared__ float sWx[38*DN];
    __shared__ float sdtw[DN*6];
    __shared__ float sdt[6*17];
    int tile = blockIdx.x & 255;
    int k    = (blockIdx.x >> 8) & 3;
    int b    = blockIdx.x >> 10;
    int t0   = tile * 16;
    int tid  = threadIdx.x;
    int base = (b*KK + k)*LL;

    for (int j = tid; j < 38*DN; j += 256) sWx[j] = xpw[k*38*DN + j];
    for (int j = tid; j < DN*6; j += 256)  sdtw[j] = dtw[k*DN*6 + j];
    for (int j = tid; j < DN*16; j += 256){
        int d = j >> 4, tt = j & 15;
        int t = t0 + tt;
        int pix;
        if (k == 0)      pix = t;
        else if (k == 1) pix = (t & 63)*64 + (t >> 6);
        else if (k == 2) pix = LL - 1 - t;
        else { int tr = LL - 1 - t; pix = (tr & 63)*64 + (tr >> 6); }
        sxs[d*17 + tt] = g_xcv[(b*DN + d)*LL + pix];
    }
    __syncthreads();
    for (int j = tid; j < DN*16; j += 256){
        int tt = j / 192, d = j % 192;
        g_xs[(base + t0 + tt)*DN + d] = sxs[d*17 + tt];
    }
    for (int j = tid; j < 38*16; j += 256){
        int c = j >> 4, tt = j & 15;
        float acc = 0.f;
        for (int dd = 0; dd < DN; dd++)
            acc = fmaf(sxs[dd*17 + tt], sWx[c*DN + dd], acc);
        if (c < RR)            sdt[c*17 + tt] = acc;
        else if (c < RR + NN)  g_bs[(base + t0 + tt)*NN + (c - RR)] = acc;
        else                   g_cs[(base + t0 + tt)*NN + (c - RR - NN)] = acc;
    }
    __syncthreads();
    for (int j = tid; j < DN*16; j += 256){
        int tt = j / 192, d = j % 192;
        float acc = dtb[k*DN + d];
        #pragma unroll
        for (int r = 0; r < RR; r++)
            acc = fmaf(sdt[r*17 + tt], sdtw[d*6 + r], acc);
        float dl = (acc > 20.f) ? acc : log1pf(__expf(acc));
        g_delta[(base + t0 + tt)*DN + d] = dl;
    }
}

// ---------------- kF1: per-segment propagator P and offset q (segments 0..6) ----------------
// block: 128 thr = 8 chains x 16 states. grid: b(4) x k(4) x s(7) x dg(24)
__global__ void kF1(const float* __restrict__ A_log){
    __shared__ float sD[16*8], sX[16*8], sB[16*16];
    int bid = blockIdx.x;
    int dg = (bid % 24) * 8;
    int s  = (bid / 24) % (SEG-1);
    int k  = (bid / (24*(SEG-1))) % 4;
    int b  = bid / (24*(SEG-1)*4);
    int tid = threadIdx.x;
    int ch = tid >> 4, n = tid & 15;
    int d  = dg + ch;
    int base = (b*KK + k)*LL + s*SEGLEN;

    float a = -__expf(A_log[(k*DN + d)*NN + n]);
    float h = 0.f, P = 1.f;

    int lt = tid >> 3, lc = tid & 7;
    float rD, rX, rB[2];
    rD = g_delta[(base + lt)*DN + dg + lc];
    rX = g_xs   [(base + lt)*DN + dg + lc];
    #pragma unroll
    for (int i = 0; i < 2; i++){
        int jj = tid + i*128;
        rB[i] = g_bs[base*NN + jj];
    }
    for (int chunk = 0; chunk < SEGLEN/16; chunk++){
        sD[tid] = rD;  sX[tid] = rX;
        sB[tid] = rB[0];  sB[tid+128] = rB[1];
        __syncthreads();
        if (chunk < SEGLEN/16 - 1){
            int t0n = (chunk + 1) * 16;
            rD = g_delta[(base + t0n + lt)*DN + dg + lc];
            rX = g_xs   [(base + t0n + lt)*DN + dg + lc];
            #pragma unroll
            for (int i = 0; i < 2; i++){
                int jj = tid + i*128;
                rB[i] = g_bs[(base + t0n)*NN + jj];
            }
        }
        #pragma unroll
        for (int t = 0; t < 16; t++){
            float dl = sD[t*8 + ch];
            float xv = sX[t*8 + ch];
            float Bn = sB[t*16 + n];
            float e  = __expf(dl * a);
            h = fmaf(e, h, dl * xv * Bn);
            P *= e;
        }
        __syncthreads();
    }
    int chain = (b*KK + k)*DN + d;
    g_P[(chain*(SEG-1) + s)*NN + n] = P;
    g_q[(chain*(SEG-1) + s)*NN + n] = h;
}

// ---------------- kF2: prefix over segments -> g_h0 ----------------
__global__ void kF2(){
    int gid = blockIdx.x*blockDim.x + threadIdx.x;   // 49152
    int chain = gid >> 4, n = gid & 15;
    float h = 0.f;
    g_h0[(chain*SEG + 0)*NN + n] = 0.f;
    #pragma unroll
    for (int s = 0; s < SEG-1; s++){
        float P = g_P[(chain*(SEG-1) + s)*NN + n];
        float q = g_q[(chain*(SEG-1) + s)*NN + n];
        h = fmaf(P, h, q);
        g_h0[(chain*SEG + s + 1)*NN + n] = h;
    }
}

// ---------------- kF3: full scan per segment with correct h0, produce y ----------------
// block: 128 thr = 8 chains x 16 states. grid: b(4) x k(4) x s(8) x dg(24)
__global__ void kF3(const float* __restrict__ A_log, const float* __restrict__ Ds){
    __shared__ float sD[16*8], sX[16*8], sB[16*16], sC[16*16], sY[16*8];
    int bid = blockIdx.x;
    int dg = (bid % 24) * 8;
    int s  = (bid / 24) % SEG;
    int k  = (bid / (24*SEG)) % 4;
    int b  = bid / (24*SEG*4);
    int tid = threadIdx.x;
    int ch = tid >> 4, n = tid & 15;
    int d  = dg + ch;
    int base = (b*KK + k)*LL + s*SEGLEN;
    int chain = (b*KK + k)*DN + d;

    float a  = -__expf(A_log[(k*DN + d)*NN + n]);
    float Dv = Ds[k*DN + d];
    float h  = g_h0[(chain*SEG + s)*NN + n];

    int lt = tid >> 3, lc = tid & 7;
    float rD, rX, rB[2], rC[2];
    rD = g_delta[(base + lt)*DN + dg + lc];
    rX = g_xs   [(base + lt)*DN + dg + lc];
    #pragma unroll
    for (int i = 0; i < 2; i++){
        int jj = tid + i*128;
        rB[i] = g_bs[base*NN + jj];
        rC[i] = g_cs[base*NN + jj];
    }
    for (int chunk = 0; chunk < SEGLEN/16; chunk++){
        sD[tid] = rD;  sX[tid] = rX;
        sB[tid] = rB[0];  sB[tid+128] = rB[1];
        sC[tid] = rC[0];  sC[tid+128] = rC[1];
        __syncthreads();
        if (chunk < SEGLEN/16 - 1){
            int t0n = (chunk + 1) * 16;
            rD = g_delta[(base + t0n + lt)*DN + dg + lc];
            rX = g_xs   [(base + t0n + lt)*DN + dg + lc];
            #pragma unroll
            for (int i = 0; i < 2; i++){
                int jj = tid + i*128;
                rB[i] = g_bs[(base + t0n)*NN + jj];
                rC[i] = g_cs[(base + t0n)*NN + jj];
            }
        }
        #pragma unroll
        for (int t = 0; t < 16; t++){
            float dl = sD[t*8 + ch];
            float xv = sX[t*8 + ch];
            float Bn = sB[t*16 + n];
            float Cn = sC[t*16 + n];
            float e  = __expf(dl * a);
            h = fmaf(e, h, dl * xv * Bn);
            float p = h * Cn;
            p += __shfl_xor_sync(0xffffffffu, p, 8);
            p += __shfl_xor_sync(0xffffffffu, p, 4);
            p += __shfl_xor_sync(0xffffffffu, p, 2);
            p += __shfl_xor_sync(0xffffffffu, p, 1);
            if (n == 0) sY[t*8 + ch] = p + Dv * xv;
        }
        __syncthreads();
        g_ys[(base + chunk*16 + lt)*DN + dg + lc] = sY[lt*8 + lc];
    }
}

// ---------------- kG: combine 4 directions + out LN + silu(z) gate -> yln ----------------
__global__ void kG(const float* __restrict__ lng, const float* __restrict__ lnb){
    int gw   = (blockIdx.x*blockDim.x + threadIdx.x) >> 5;
    int lane = threadIdx.x & 31;
    for (int q = 0; q < 8; q++){
        int pg = gw*8 + q;
        int b  = pg >> 12;
        int l  = pg & 4095;
        int hh = l >> 6, ww = l & 63;
        int t1 = ww*64 + hh;
        int b4 = b*KK*LL;
        float y[6], zf[6];
        float s = 0.f, s2 = 0.f;
        #pragma unroll
        for (int i = 0; i < 6; i++){
            int dd = lane + i*32;
            float v = g_ys[(b4 + 0*LL + l)*DN + dd]
                    + g_ys[(b4 + 2*LL + (LL-1-l))*DN + dd]
                    + g_ys[(b4 + 1*LL + t1)*DN + dd]
                    + g_ys[(b4 + 3*LL + (LL-1-t1))*DN + dd];
            y[i]  = v;  s += v;  s2 += v*v;
            zf[i] = g_z[(b*LL + l)*DN + dd];
        }
        #pragma unroll
        for (int off = 16; off > 0; off >>= 1){
            s  += __shfl_xor_sync(0xffffffffu, s,  off);
            s2 += __shfl_xor_sync(0xffffffffu, s2, off);
        }
        float m   = s * (1.f/192.f);
        float var = s2 * (1.f/192.f) - m*m;
        float rstd = rsqrtf(var + 1e-5f);
        #pragma unroll
        for (int i = 0; i < 6; i++){
            int dd = lane + i*32;
            float yn = (y[i] - m) * rstd * lng[dd] + lnb[dd];
            g_yln[(b*LL + l)*DN + dd] = yn * siluf(zf[i]);
        }
    }
}

// ---------------- kH: out_proj (192 -> 96) -> g_dd (b,pix,96) ----------------
__global__ void kH(const float* __restrict__ w, const float* __restrict__ bias){
    __shared__ float sA[16*193];
    __shared__ float sW[32*192];
    __shared__ float sO[32*17];
    int b = blockIdx.x >> 8;
    int pix0 = (blockIdx.x & 255) * 16;
    int tid = threadIdx.x;
    for (int j = tid; j < 16*DN; j += 256){
        int p = j / 192, c = j % 192;
        sA[p*193 + c] = g_yln[(b*LL + pix0 + p)*DN + c];
    }
    int p = tid & 15, og = tid >> 4;
    for (int ch = 0; ch < 3; ch++){
        __syncthreads();
        for (int j = tid; j < 32*192; j += 256) sW[j] = w[ch*32*192 + j];
        __syncthreads();
        float acc[2];
        acc[0] = bias[ch*32 + og*2 + 0];
        acc[1] = bias[ch*32 + og*2 + 1];
        for (int kk = 0; kk < DN; kk++){
            float av = sA[p*193 + kk];
            acc[0] = fmaf(av, sW[(og*2+0)*DN + kk], acc[0]);
            acc[1] = fmaf(av, sW[(og*2+1)*DN + kk], acc[1]);
        }
        sO[(og*2+0)*17 + p] = acc[0];
        sO[(og*2+1)*17 + p] = acc[1];
        __syncthreads();
        for (int j = tid; j < 16*32; j += 256){
            int pp = j >> 5, o = j & 31;
            g_dd[(b*LL + pix0 + pp)*CHID + ch*32 + o] = sO[o*17 + pp];
        }
    }
}

// ---------------- kI: up + bn + silu + residual + gate -> out ----------------
__global__ void kI(const float* __restrict__ w, const float* __restrict__ bias,
                   const float* __restrict__ bng, const float* __restrict__ bnb,
                   float* __restrict__ out){
    __shared__ float sA[32*97];
    __shared__ float sW[64*96];
    __shared__ float sO[64*33];
    int b = blockIdx.x >> 7;
    int pix0 = (blockIdx.x & 127) * 32;
    int tid = threadIdx.x;
    for (int j = tid; j < 64*96; j += 256) sW[j] = w[j];
    for (int j = tid; j < 32*CHID; j += 256){
        int p = j / 96, c = j % 96;
        sA[p*97 + c] = g_dd[(b*LL + pix0 + p)*CHID + c];
    }
    __syncthreads();
    int p = tid & 31, og = tid >> 5;
    float acc[8];
    #pragma unroll
    for (int j = 0; j < 8; j++) acc[j] = bias[og*8 + j];
    for (int kk = 0; kk < CHID; kk++){
        float a = sA[p*97 + kk];
        #pragma unroll
        for (int j = 0; j < 8; j++)
            acc[j] = fmaf(a, sW[(og*8+j)*96 + kk], acc[j]);
    }
    #pragma unroll
    for (int j = 0; j < 8; j++){
        int o = og*8 + j;
        float inv = bng[o] * rsqrtf(1.00001f);
        float t = acc[j] * inv + bnb[o];
        sO[o*33 + p] = siluf(t);
    }
    __syncthreads();
    for (int j = tid; j < 64*32; j += 256){
        int o = j >> 5, pp = j & 31;
        int idx = (b*CIN + o)*LL + pix0 + pp;
        out[idx] = (sO[o*33 + pp] + g_diff[idx]) * g_gate[idx];
    }
}

// ---------------- launcher ----------------
extern "C" void kernel_launch(void* const* d_in, const int* in_sizes, int n_in,
                              void* d_out, int out_size){
    const float* pre        = (const float*)d_in[0];
    const float* post       = (const float*)d_in[1];
    const float* prepost_w  = (const float*)d_in[2];
    const float* prepost_b  = (const float*)d_in[3];
    const float* prepost_g  = (const float*)d_in[4];
    const float* prepost_bb = (const float*)d_in[5];
    const float* down_w     = (const float*)d_in[6];
    const float* down_b     = (const float*)d_in[7];
    const float* down_g     = (const float*)d_in[8];
    const float* down_bb    = (const float*)d_in[9];
    const float* up_w       = (const float*)d_in[10];
    const float* up_b       = (const float*)d_in[11];
    const float* up_g       = (const float*)d_in[12];
    const float* up_bb      = (const float*)d_in[13];
    const float* pe_w       = (const float*)d_in[14];
    const float* pe_b       = (const float*)d_in[15];
    const float* pe_ln_g    = (const float*)d_in[16];
    const float* pe_ln_b    = (const float*)d_in[17];
    const float* in_proj_w  = (const float*)d_in[18];
    const float* in_proj_b  = (const float*)d_in[19];
    const float* conv_w     = (const float*)d_in[20];
    const float* conv_b     = (const float*)d_in[21];
    const float* x_proj_w   = (const float*)d_in[22];
    const float* dt_w       = (const float*)d_in[23];
    const float* dt_b       = (const float*)d_in[24];
    const float* A_log      = (const float*)d_in[25];
    const float* Ds         = (const float*)d_in[26];
    const float* out_ln_g   = (const float*)d_in[27];
    const float* out_ln_b   = (const float*)d_in[28];
    const float* out_proj_w = (const float*)d_in[29];
    const float* out_proj_b = (const float*)d_in[30];
    float* out = (float*)d_out;

    kDiff<<<BB*CIN*LL/4/256, 256>>>(pre, post);
    kGate2<<<BB*(LL/32), 256>>>(pre, post, prepost_w, prepost_b, prepost_g, prepost_bb);
    kB<<<BB*(LL/32), 256>>>(down_w, down_b, down_g, down_bb);
    kC<<<BB*(LL/16), 256>>>(pe_w, pe_b, pe_ln_g, pe_ln_b);
    kD<<<BB*(LL/32), 256>>>(in_proj_w, in_proj_b);
    kE<<<BB*DN*4, 256>>>(conv_w, conv_b);
    kX<<<BB*KK*(LL/16), 256>>>(x_proj_w, dt_w, dt_b);
    kF1<<<BB*KK*(SEG-1)*(DN/8), 128>>>(A_log);
    kF2<<<(BB*KK*DN*NN)/256, 256>>>();
    kF3<<<BB*KK*SEG*(DN/8), 128>>>(A_log, Ds);
    kG<<<256, 256>>>(out_ln_g, out_ln_b);
    kH<<<BB*(LL/16), 256>>>(out_proj_w, out_proj_b);
    kI<<<BB*(LL/32), 256>>>(up_w, up_b, up_g, up_bb, out);
}